// round 13
// baseline (speedup 1.0000x reference)
#include <cuda_runtime.h>
#include <math.h>
#include <stdint.h>

#define Bq 32
#define Vq 2048
#define Pq 64
#define Aq 8
#define Fq 72          // P + A
#define NFq 128
#define TWOF 144       // 2*F
#define NPC 64         // partial slots per batch (= 16 chunks * 4 subsets)

// Scratch (device globals; no allocation allowed)
__device__ uint32_t g_aggT [Bq * Vq * Aq];             // agg in tf32
__device__ uint32_t g_MT   [Bq * NFq * Aq];            // M transposed, tf32
__device__ uint32_t g_W12T [Fq * 64];                  // [n][k] tf32 (W1|W2)^T
__device__ uint32_t g_WoutT[NFq * 64];                 // [n][k] tf32 Wout_top^T
__device__ float    g_pmax [Bq * NPC * Aq * Fq];
__device__ float    g_psum [Bq * NPC * Aq * Fq];
__device__ unsigned g_cnt  [Bq];                       // zero-initialized

__device__ __forceinline__ uint32_t f2tf32(float f) {
    uint32_t r; asm("cvt.rna.tf32.f32 %0, %1;" : "=r"(r) : "f"(f)); return r;
}
__device__ __forceinline__ void mma_tf32(float* d, const uint32_t* a, const uint32_t* b) {
    asm("mma.sync.aligned.m16n8k8.row.col.f32.tf32.tf32.f32 "
        "{%0,%1,%2,%3},{%4,%5,%6,%7},{%8,%9},{%0,%1,%2,%3};"
        : "+f"(d[0]), "+f"(d[1]), "+f"(d[2]), "+f"(d[3])
        : "r"(a[0]), "r"(a[1]), "r"(a[2]), "r"(a[3]), "r"(b[0]), "r"(b[1]));
}
__device__ __forceinline__ uint32_t s2u(const void* p) {
    return (uint32_t)__cvta_generic_to_shared(p);
}
__device__ __forceinline__ void ldsm4(uint32_t* r, uint32_t addr) {
    asm volatile("ldmatrix.sync.aligned.m8n8.x4.shared.b16 {%0,%1,%2,%3}, [%4];"
                 : "=r"(r[0]), "=r"(r[1]), "=r"(r[2]), "=r"(r[3]) : "r"(addr));
}
__device__ __forceinline__ void ldsm2(uint32_t* r, uint32_t addr) {
    asm volatile("ldmatrix.sync.aligned.m8n8.x2.shared.b16 {%0,%1}, [%2];"
                 : "=r"(r[0]), "=r"(r[1]) : "r"(addr));
}
__device__ __forceinline__ uint32_t cvt_reg(uint32_t raw) {
    return f2tf32(__uint_as_float(raw));
}
__device__ __forceinline__ float ftanh(float x) {
    float e = __expf(2.0f * x);
    return 1.0f - __fdividef(2.0f, e + 1.0f);
}
__device__ __forceinline__ void cpasync16(uint32_t dst, const void* src) {
    asm volatile("cp.async.cg.shared.global [%0], [%1], 16;" :: "r"(dst), "l"(src));
}

// ---------------------------------------------------------------------------
// kT: one-time transpose + tf32 conversion of weights.
// ---------------------------------------------------------------------------
__global__ void __launch_bounds__(256)
kT(const float* __restrict__ W1, const float* __restrict__ W2,
   const float* __restrict__ Wout) {
    const int i = blockIdx.x * 256 + threadIdx.x;
    if (i < Fq * 64) {
        int n = i >> 6, k = i & 63;
        float v = (n < Pq) ? W1[k * Pq + n] : W2[k * Aq + (n - Pq)];
        g_W12T[i] = f2tf32(v);
    }
    {
        int n = i >> 6, k = i & 63;
        g_WoutT[i] = f2tf32(Wout[k * NFq + n]);
    }
}

// ---------------------------------------------------------------------------
// k1: grid 256, 2 tiles (128 rows) per CTA, double-buffered raw-fp32 X via
// cp.async; A fragments converted to tf32 in registers after ldsm.
// Wt staged once per CTA. Last CTA of each batch inlines the kB2 combine.
// 576 threads = 18 warps. MMA: warps 0-15 (8 rg x 2 ng). Reduce: 4 subsets.
// ---------------------------------------------------------------------------
#define XS1 68         // word stride of X rows
#define SFS 80         // float stride of feats tile
#define BUF1 10240     // words per X/sf buffer (128*80)
__global__ void __launch_bounds__(576)
k1(const float* __restrict__ X,
   const float* __restrict__ b1, const float* __restrict__ b2,
   const float* __restrict__ Wout) {
    extern __shared__ uint32_t smu[];
    uint32_t* Wt = smu + 2 * BUF1;            // [72][68]
    float*    bs = (float*)(Wt + Fq * XS1);   // [72]
    __shared__ unsigned s_flag;

    const int tid = threadIdx.x;
    const int bid = blockIdx.x;
    const int wid = tid >> 5, lane = tid & 31;
    const int lq = lane & 3, lg = lane >> 2;
    const int rA = lane & 15;
    const int cA = (lane & 16) >> 2;
    const int rB = (lane & 7) + ((lane & 16) >> 1);
    const int cB = (lane & 8) >> 1;

    // prologue: group0 = Wt + X(t0); group1 = X(t1)
    for (int i = tid; i < Fq * 16; i += 576) {
        int n = i >> 4, c = i & 15;
        cpasync16(s2u(Wt + n * XS1 + c * 4), g_W12T + n * 64 + c * 4);
    }
    {
        const float* src = X + (long)(bid * 2) * 128 * Pq;
        for (int i = tid; i < 128 * 16; i += 576) {
            int r = i >> 4, c = i & 15;
            cpasync16(s2u(smu + r * XS1 + c * 4), src + r * Pq + c * 4);
        }
    }
    asm volatile("cp.async.commit_group;");
    {
        const float* src = X + (long)(bid * 2 + 1) * 128 * Pq;
        for (int i = tid; i < 128 * 16; i += 576) {
            int r = i >> 4, c = i & 15;
            cpasync16(s2u(smu + BUF1 + r * XS1 + c * 4), src + r * Pq + c * 4);
        }
    }
    asm volatile("cp.async.commit_group;");
    if (tid < Fq) bs[tid] = (tid < Pq) ? b1[tid] : b2[tid - Pq];

#pragma unroll
    for (int j = 0; j < 2; j++) {
        const int tile = bid * 2 + j;
        const long row0 = (long)tile * 128;
        const int b = tile >> 4, chunk = tile & 15;
        uint32_t* xb = smu + j * BUF1;
        float*    sf = (float*)xb;

        if (j == 0) asm volatile("cp.async.wait_group 1;");
        else        asm volatile("cp.async.wait_group 0;");
        __syncthreads();

        float d[5][4];
        const int rg = wid & 7, wg = wid >> 3;
        if (wid < 16) {
            uint32_t aAddr = s2u(xb + (rg * 16 + rA) * XS1 + cA);
#pragma unroll
            for (int nt = 0; nt < 5; nt++)
#pragma unroll
                for (int r = 0; r < 4; r++) d[nt][r] = 0.f;

            if (wg == 0) {
                uint32_t b0  = s2u(Wt + (0  + rB) * XS1 + cB);
                uint32_t b1a = s2u(Wt + (16 + rB) * XS1 + cB);
                uint32_t b2a = s2u(Wt + (32 + (lane & 7)) * XS1 + cB);
#pragma unroll
                for (int ks = 0; ks < 8; ks++) {
                    uint32_t a[4];
                    ldsm4(a, aAddr); aAddr += 32;
#pragma unroll
                    for (int r = 0; r < 4; r++) a[r] = cvt_reg(a[r]);
                    uint32_t bf[5][2];
                    ldsm4(&bf[0][0], b0);  b0  += 32;
                    ldsm4(&bf[2][0], b1a); b1a += 32;
                    ldsm2(bf[4], b2a);     b2a += 32;
#pragma unroll
                    for (int nt = 0; nt < 5; nt++) mma_tf32(d[nt], a, bf[nt]);
                }
            } else {
                uint32_t b0  = s2u(Wt + (40 + rB) * XS1 + cB);
                uint32_t b1a = s2u(Wt + (56 + rB) * XS1 + cB);
#pragma unroll
                for (int ks = 0; ks < 8; ks++) {
                    uint32_t a[4];
                    ldsm4(a, aAddr); aAddr += 32;
#pragma unroll
                    for (int r = 0; r < 4; r++) a[r] = cvt_reg(a[r]);
                    uint32_t bf[4][2];
                    ldsm4(&bf[0][0], b0);  b0  += 32;
                    ldsm4(&bf[2][0], b1a); b1a += 32;
#pragma unroll
                    for (int nt = 0; nt < 4; nt++) mma_tf32(d[nt], a, bf[nt]);
                }
            }
        }
        __syncthreads();   // all X reads done; safe to overwrite with sf

        if (wid < 16) {
            const int orow = rg * 16 + lg;
            if (wg == 0) {
#pragma unroll
                for (int nt = 0; nt < 5; nt++) {
                    const int col = nt * 8 + 2 * lq;
                    *(float2*)&sf[orow * SFS + col] =
                        make_float2(d[nt][0] + bs[col], d[nt][1] + bs[col + 1]);
                    *(float2*)&sf[(orow + 8) * SFS + col] =
                        make_float2(d[nt][2] + bs[col], d[nt][3] + bs[col + 1]);
                }
            } else {
#pragma unroll
                for (int nt = 0; nt < 3; nt++) {
                    const int col = (nt + 5) * 8 + 2 * lq;
                    *(float2*)&sf[orow * SFS + col] =
                        make_float2(d[nt][0] + bs[col], d[nt][1] + bs[col + 1]);
                    *(float2*)&sf[(orow + 8) * SFS + col] =
                        make_float2(d[nt][2] + bs[col], d[nt][3] + bs[col + 1]);
                }
                {   // agg cols 64..71
                    const int col = 64 + 2 * lq;
                    float e0 = __expf(-fabsf(d[3][0] + bs[col]));
                    float e1 = __expf(-fabsf(d[3][1] + bs[col + 1]));
                    float e2 = __expf(-fabsf(d[3][2] + bs[col]));
                    float e3 = __expf(-fabsf(d[3][3] + bs[col + 1]));
                    *(float2*)&sf[orow * SFS + col]       = make_float2(e0, e1);
                    *(float2*)&sf[(orow + 8) * SFS + col] = make_float2(e2, e3);
                    *(uint2*)(g_aggT + (row0 + orow) * Aq + 2 * lq) =
                        make_uint2(f2tf32(e0), f2tf32(e1));
                    *(uint2*)(g_aggT + (row0 + orow + 8) * Aq + 2 * lq) =
                        make_uint2(f2tf32(e2), f2tf32(e3));
                }
            }
        }
        __syncthreads();

        // partial reduce: 4 subsets of 32 v; thread -> (a, f4 quad)
        {
            const int sub = tid / 144;
            const int t   = tid % 144;
            const int a8  = t & 7;
            const int f4  = t >> 3;
            const int vbase = sub * 32;

            float4 mx = make_float4(-INFINITY, -INFINITY, -INFINITY, -INFINITY);
            float4 sv = make_float4(0.f, 0.f, 0.f, 0.f);
#pragma unroll 8
            for (int i = 0; i < 32; i++) {
                const int v = vbase + i;
                float e = sf[v * SFS + 64 + a8];
                float4 x = *(float4*)&sf[v * SFS + f4 * 4];
                float p0 = e * x.x, p1 = e * x.y, p2 = e * x.z, p3 = e * x.w;
                mx.x = fmaxf(mx.x, p0); mx.y = fmaxf(mx.y, p1);
                mx.z = fmaxf(mx.z, p2); mx.w = fmaxf(mx.w, p3);
                sv.x += p0; sv.y += p1; sv.z += p2; sv.w += p3;
            }
            const int pc = chunk * 4 + sub;
            const long o = (((long)b * NPC + pc) * Aq + a8) * Fq + f4 * 4;
            *(float4*)(g_pmax + o) = mx;
            *(float4*)(g_psum + o) = sv;
        }
        __syncthreads();
    }

    // ---- last CTA per batch: combine partials -> collapsed -> MT (inline kB2) ----
    {
        const int b = bid >> 3;          // 8 CTAs per batch
        __threadfence();
        __syncthreads();
        if (tid == 0) {
            unsigned old = atomicAdd(&g_cnt[b], 1u);
            s_flag = (old == 7u) ? 1u : 0u;
            if (old == 7u) atomicExch(&g_cnt[b], 0u);   // reset for graph replay
        }
        __syncthreads();
        if (s_flag) {
            __threadfence();             // acquire side
            float* scol = (float*)smu;   // [8][144], buffer 0 is free
            const int a = tid % Aq;
            const int f = tid / Aq;      // 576 = 8 * 72 exactly
            {
                float vmax = -INFINITY, vsum = 0.f;
                const long base = ((long)b * NPC) * Aq * Fq + a * Fq + f;
#pragma unroll 8
                for (int pc = 0; pc < NPC; pc++) {
                    vmax = fmaxf(vmax, g_pmax[base + (long)pc * Aq * Fq]);
                    vsum += g_psum[base + (long)pc * Aq * Fq];
                }
                scol[a * TWOF + f]      = vmax;
                scol[a * TWOF + Fq + f] = vsum * (1.0f / (float)Vq);
            }
            __syncthreads();
            for (int idx = tid; idx < Aq * NFq; idx += 576) {
                int aa = idx / NFq, n = idx % NFq;
                float acc = Wout[(Pq + Aq * TWOF + aa) * NFq + n];
#pragma unroll 16
                for (int g = 0; g < TWOF; g++) {
                    acc = fmaf(scol[aa * TWOF + g], Wout[(Pq + aa * TWOF + g) * NFq + n], acc);
                }
                g_MT[((long)b * NFq + n) * Aq + aa] = f2tf32(acc);
            }
        }
    }
}

// ---------------------------------------------------------------------------
// k3: grid 256, 2 tiles (128 rows) per CTA, b constant per CTA -> Wt staged
// once. X raw via cp.async, A frags converted in registers after ldsm
// (agg cols already tf32: cvt idempotent). 512 threads = 16 warps (4m x 4n).
// ---------------------------------------------------------------------------
#define XS3 76
__global__ void __launch_bounds__(512)
k3(const float* __restrict__ X, const float* __restrict__ bout,
   float* __restrict__ out) {
    extern __shared__ uint32_t sm3[];
    uint32_t* Xs = sm3;                   // [128][76]: cols 0-63 X(raw), 64-71 agg(tf32)
    uint32_t* Wt = Xs + 128 * XS3;        // [128][76]
    float*    bC = (float*)(Wt + 128 * XS3);

    const int tid = threadIdx.x;
    const int bid = blockIdx.x;
    const int b   = bid >> 3;
    const int wid = tid >> 5, lane = tid & 31;
    const int wm = (wid >> 2) & 3, wn = wid & 3;
    const int lq = lane & 3, lg = lane >> 2;
    const int rA = lane & 15;
    const int cA = (lane & 16) >> 2;
    const int rB = (lane & 7) + ((lane & 16) >> 1);
    const int cB = (lane & 8) >> 1;

    // prologue: Wt (WoutT + MT) + tile-0 X/agg
    for (int i = tid; i < NFq * 16; i += 512) {
        int n = i >> 4, c = i & 15;
        cpasync16(s2u(Wt + n * XS3 + c * 4), g_WoutT + n * 64 + c * 4);
    }
    for (int i = tid; i < NFq * 2; i += 512) {
        int n = i >> 1, c = i & 1;
        cpasync16(s2u(Wt + n * XS3 + 64 + c * 4),
                  g_MT + ((long)b * NFq + n) * Aq + c * 4);
    }
    {
        const long row0 = (long)(bid * 2) * 128;
        for (int i = tid; i < 128 * 16; i += 512) {
            int r = i >> 4, c = i & 15;
            cpasync16(s2u(Xs + r * XS3 + c * 4), X + (row0 + r) * Pq + c * 4);
        }
        for (int i = tid; i < 128 * 2; i += 512) {
            int r = i >> 1, c = i & 1;
            cpasync16(s2u(Xs + r * XS3 + 64 + c * 4), g_aggT + (row0 + r) * Aq + c * 4);
        }
    }
    asm volatile("cp.async.commit_group;");
    if (tid < NFq) bC[tid] = bout[tid];

#pragma unroll
    for (int j = 0; j < 2; j++) {
        const int tile = bid * 2 + j;
        const long row0 = (long)tile * 128;

        asm volatile("cp.async.wait_group 0;");
        __syncthreads();

        uint32_t aAddr[2], bAddr[2];
#pragma unroll
        for (int mt = 0; mt < 2; mt++)
            aAddr[mt] = s2u(Xs + (wm * 32 + mt * 16 + rA) * XS3 + cA);
#pragma unroll
        for (int p = 0; p < 2; p++)
            bAddr[p] = s2u(Wt + (wn * 32 + p * 16 + rB) * XS3 + cB);

        float d[2][4][4];
#pragma unroll
        for (int mt = 0; mt < 2; mt++)
#pragma unroll
            for (int nt = 0; nt < 4; nt++)
#pragma unroll
                for (int r = 0; r < 4; r++) d[mt][nt][r] = 0.f;

#pragma unroll
        for (int ks = 0; ks < 9; ks++) {
            uint32_t a[2][4];
#pragma unroll
            for (int mt = 0; mt < 2; mt++) {
                ldsm4(a[mt], aAddr[mt]); aAddr[mt] += 32;
            }
#pragma unroll
            for (int mt = 0; mt < 2; mt++)
#pragma unroll
                for (int r = 0; r < 4; r++) a[mt][r] = cvt_reg(a[mt][r]);
            uint32_t bf[4][2];
#pragma unroll
            for (int p = 0; p < 2; p++) {
                ldsm4(&bf[2 * p][0], bAddr[p]); bAddr[p] += 32;
            }
#pragma unroll
            for (int mt = 0; mt < 2; mt++)
#pragma unroll
                for (int nt = 0; nt < 4; nt++)
                    mma_tf32(d[mt][nt], a[mt], bf[nt]);
        }
        __syncthreads();   // Xs reads done

        if (j == 0) {      // prefetch tile 1 X/agg; overlaps epilogue below
            const long nrow0 = (long)(tile + 1) * 128;
            for (int i = tid; i < 128 * 16; i += 512) {
                int r = i >> 4, c = i & 15;
                cpasync16(s2u(Xs + r * XS3 + c * 4), X + (nrow0 + r) * Pq + c * 4);
            }
            for (int i = tid; i < 128 * 2; i += 512) {
                int r = i >> 1, c = i & 1;
                cpasync16(s2u(Xs + r * XS3 + 64 + c * 4), g_aggT + (nrow0 + r) * Aq + c * 4);
            }
            asm volatile("cp.async.commit_group;");
        }

#pragma unroll
        for (int mt = 0; mt < 2; mt++) {
            const long r0 = row0 + wm * 32 + mt * 16 + lg;
#pragma unroll
            for (int nt = 0; nt < 4; nt++) {
                const int c0 = wn * 32 + nt * 8 + 2 * lq;
                float2 o0, o1;
                o0.x = ftanh(d[mt][nt][0] + bC[c0]);
                o0.y = ftanh(d[mt][nt][1] + bC[c0 + 1]);
                o1.x = ftanh(d[mt][nt][2] + bC[c0]);
                o1.y = ftanh(d[mt][nt][3] + bC[c0 + 1]);
                *(float2*)(out + (r0)     * NFq + c0) = o0;
                *(float2*)(out + (r0 + 8) * NFq + c0) = o1;
            }
        }
    }
}

// ---------------------------------------------------------------------------
extern "C" void kernel_launch(void* const* d_in, const int* in_sizes, int n_in,
                              void* d_out, int out_size) {
    const float* X    = (const float*)d_in[0];
    const float* W1   = (const float*)d_in[1];
    const float* b1   = (const float*)d_in[2];
    const float* W2   = (const float*)d_in[3];
    const float* b2   = (const float*)d_in[4];
    const float* Wout = (const float*)d_in[5];
    const float* bout = (const float*)d_in[6];
    float* out = (float*)d_out;

    const int smem1 = (2 * BUF1 + Fq * XS1 + 80) * 4;          // ~101.8 KB
    const int smem3 = (128 * XS3 * 2) * 4 + NFq * 4;           // ~78.3 KB
    cudaFuncSetAttribute(k1, cudaFuncAttributeMaxDynamicSharedMemorySize, smem1);
    cudaFuncSetAttribute(k3, cudaFuncAttributeMaxDynamicSharedMemorySize, smem3);

    kT<<<32, 256>>>(W1, W2, Wout);

    k1<<<(Bq * Vq) / 256, 576, smem1>>>(X, b1, b2, Wout);

    k3<<<(Bq * Vq) / 256, 512, smem3>>>(X, bout, out);
}

// round 14
// speedup vs baseline: 1.3900x; 1.3900x over previous
#include <cuda_runtime.h>
#include <math.h>
#include <stdint.h>

#define Bq 32
#define Vq 2048
#define Pq 64
#define Aq 8
#define Fq 72          // P + A
#define NFq 128
#define TWOF 144       // 2*F
#define NPC 64         // partial slots per batch (= 16 chunks * 4 subsets)

// Scratch (device globals; no allocation allowed)
__device__ uint32_t g_aggT [Bq * Vq * Aq];             // agg in tf32
__device__ uint32_t g_MT   [Bq * NFq * Aq];            // M transposed, tf32
__device__ uint32_t g_W12T [Fq * 64];                  // [n][k] tf32 (W1|W2)^T
__device__ uint32_t g_WoutT[NFq * 64];                 // [n][k] tf32 Wout_top^T
__device__ float    g_pmax [Bq * NPC * Aq * Fq];
__device__ float    g_psum [Bq * NPC * Aq * Fq];

__device__ __forceinline__ uint32_t f2tf32(float f) {
    uint32_t r; asm("cvt.rna.tf32.f32 %0, %1;" : "=r"(r) : "f"(f)); return r;
}
__device__ __forceinline__ void mma_tf32(float* d, const uint32_t* a, const uint32_t* b) {
    asm("mma.sync.aligned.m16n8k8.row.col.f32.tf32.tf32.f32 "
        "{%0,%1,%2,%3},{%4,%5,%6,%7},{%8,%9},{%0,%1,%2,%3};"
        : "+f"(d[0]), "+f"(d[1]), "+f"(d[2]), "+f"(d[3])
        : "r"(a[0]), "r"(a[1]), "r"(a[2]), "r"(a[3]), "r"(b[0]), "r"(b[1]));
}
__device__ __forceinline__ uint32_t s2u(const void* p) {
    return (uint32_t)__cvta_generic_to_shared(p);
}
__device__ __forceinline__ void ldsm4(uint32_t* r, uint32_t addr) {
    asm volatile("ldmatrix.sync.aligned.m8n8.x4.shared.b16 {%0,%1,%2,%3}, [%4];"
                 : "=r"(r[0]), "=r"(r[1]), "=r"(r[2]), "=r"(r[3]) : "r"(addr));
}
__device__ __forceinline__ void ldsm2(uint32_t* r, uint32_t addr) {
    asm volatile("ldmatrix.sync.aligned.m8n8.x2.shared.b16 {%0,%1}, [%2];"
                 : "=r"(r[0]), "=r"(r[1]) : "r"(addr));
}
__device__ __forceinline__ uint32_t cvt_reg(uint32_t raw) {
    return f2tf32(__uint_as_float(raw));
}
__device__ __forceinline__ float ftanh(float x) {
    float e = __expf(2.0f * x);
    return 1.0f - __fdividef(2.0f, e + 1.0f);
}
__device__ __forceinline__ void cpasync16(uint32_t dst, const void* src) {
    asm volatile("cp.async.cg.shared.global [%0], [%1], 16;" :: "r"(dst), "l"(src));
}

// ---------------------------------------------------------------------------
// kT: one-time transpose + tf32 conversion of weights.
// ---------------------------------------------------------------------------
__global__ void __launch_bounds__(256)
kT(const float* __restrict__ W1, const float* __restrict__ W2,
   const float* __restrict__ Wout) {
    const int i = blockIdx.x * 256 + threadIdx.x;
    if (i < Fq * 64) {
        int n = i >> 6, k = i & 63;
        float v = (n < Pq) ? W1[k * Pq + n] : W2[k * Aq + (n - Pq)];
        g_W12T[i] = f2tf32(v);
    }
    {
        int n = i >> 6, k = i & 63;
        g_WoutT[i] = f2tf32(Wout[k * NFq + n]);
    }
}

// ---------------------------------------------------------------------------
// k1: grid 256, 2 tiles (128 rows) per CTA, double-buffered raw-fp32 X via
// cp.async; A fragments converted to tf32 in registers after ldsm.
// Wt staged once per CTA. 576 threads = 18 warps. MMA: warps 0-15.
// ---------------------------------------------------------------------------
#define XS1 68         // word stride of X rows
#define SFS 80         // float stride of feats tile
#define BUF1 10240     // words per X/sf buffer (128*80)
__global__ void __launch_bounds__(576)
k1(const float* __restrict__ X,
   const float* __restrict__ b1, const float* __restrict__ b2) {
    extern __shared__ uint32_t smu[];
    uint32_t* Wt = smu + 2 * BUF1;            // [72][68]
    float*    bs = (float*)(Wt + Fq * XS1);   // [72]

    const int tid = threadIdx.x;
    const int bid = blockIdx.x;
    const int wid = tid >> 5, lane = tid & 31;
    const int lq = lane & 3, lg = lane >> 2;
    const int rA = lane & 15;
    const int cA = (lane & 16) >> 2;
    const int rB = (lane & 7) + ((lane & 16) >> 1);
    const int cB = (lane & 8) >> 1;

    // prologue: group0 = Wt + X(t0); group1 = X(t1)
    for (int i = tid; i < Fq * 16; i += 576) {
        int n = i >> 4, c = i & 15;
        cpasync16(s2u(Wt + n * XS1 + c * 4), g_W12T + n * 64 + c * 4);
    }
    {
        const float* src = X + (long)(bid * 2) * 128 * Pq;
        for (int i = tid; i < 128 * 16; i += 576) {
            int r = i >> 4, c = i & 15;
            cpasync16(s2u(smu + r * XS1 + c * 4), src + r * Pq + c * 4);
        }
    }
    asm volatile("cp.async.commit_group;");
    {
        const float* src = X + (long)(bid * 2 + 1) * 128 * Pq;
        for (int i = tid; i < 128 * 16; i += 576) {
            int r = i >> 4, c = i & 15;
            cpasync16(s2u(smu + BUF1 + r * XS1 + c * 4), src + r * Pq + c * 4);
        }
    }
    asm volatile("cp.async.commit_group;");
    if (tid < Fq) bs[tid] = (tid < Pq) ? b1[tid] : b2[tid - Pq];

#pragma unroll
    for (int j = 0; j < 2; j++) {
        const int tile = bid * 2 + j;
        const long row0 = (long)tile * 128;
        const int b = tile >> 4, chunk = tile & 15;
        uint32_t* xb = smu + j * BUF1;
        float*    sf = (float*)xb;

        if (j == 0) asm volatile("cp.async.wait_group 1;");
        else        asm volatile("cp.async.wait_group 0;");
        __syncthreads();

        float d[5][4];
        const int rg = wid & 7, wg = wid >> 3;
        if (wid < 16) {
            uint32_t aAddr = s2u(xb + (rg * 16 + rA) * XS1 + cA);
#pragma unroll
            for (int nt = 0; nt < 5; nt++)
#pragma unroll
                for (int r = 0; r < 4; r++) d[nt][r] = 0.f;

            if (wg == 0) {
                uint32_t b0  = s2u(Wt + (0  + rB) * XS1 + cB);
                uint32_t b1a = s2u(Wt + (16 + rB) * XS1 + cB);
                uint32_t b2a = s2u(Wt + (32 + (lane & 7)) * XS1 + cB);
#pragma unroll
                for (int ks = 0; ks < 8; ks++) {
                    uint32_t a[4];
                    ldsm4(a, aAddr); aAddr += 32;
#pragma unroll
                    for (int r = 0; r < 4; r++) a[r] = cvt_reg(a[r]);
                    uint32_t bf[5][2];
                    ldsm4(&bf[0][0], b0);  b0  += 32;
                    ldsm4(&bf[2][0], b1a); b1a += 32;
                    ldsm2(bf[4], b2a);     b2a += 32;
#pragma unroll
                    for (int nt = 0; nt < 5; nt++) mma_tf32(d[nt], a, bf[nt]);
                }
            } else {
                uint32_t b0  = s2u(Wt + (40 + rB) * XS1 + cB);
                uint32_t b1a = s2u(Wt + (56 + rB) * XS1 + cB);
#pragma unroll
                for (int ks = 0; ks < 8; ks++) {
                    uint32_t a[4];
                    ldsm4(a, aAddr); aAddr += 32;
#pragma unroll
                    for (int r = 0; r < 4; r++) a[r] = cvt_reg(a[r]);
                    uint32_t bf[4][2];
                    ldsm4(&bf[0][0], b0);  b0  += 32;
                    ldsm4(&bf[2][0], b1a); b1a += 32;
#pragma unroll
                    for (int nt = 0; nt < 4; nt++) mma_tf32(d[nt], a, bf[nt]);
                }
            }
        }
        __syncthreads();   // all X reads done; safe to overwrite with sf

        if (wid < 16) {
            const int orow = rg * 16 + lg;
            if (wg == 0) {
#pragma unroll
                for (int nt = 0; nt < 5; nt++) {
                    const int col = nt * 8 + 2 * lq;
                    *(float2*)&sf[orow * SFS + col] =
                        make_float2(d[nt][0] + bs[col], d[nt][1] + bs[col + 1]);
                    *(float2*)&sf[(orow + 8) * SFS + col] =
                        make_float2(d[nt][2] + bs[col], d[nt][3] + bs[col + 1]);
                }
            } else {
#pragma unroll
                for (int nt = 0; nt < 3; nt++) {
                    const int col = (nt + 5) * 8 + 2 * lq;
                    *(float2*)&sf[orow * SFS + col] =
                        make_float2(d[nt][0] + bs[col], d[nt][1] + bs[col + 1]);
                    *(float2*)&sf[(orow + 8) * SFS + col] =
                        make_float2(d[nt][2] + bs[col], d[nt][3] + bs[col + 1]);
                }
                {   // agg cols 64..71
                    const int col = 64 + 2 * lq;
                    float e0 = __expf(-fabsf(d[3][0] + bs[col]));
                    float e1 = __expf(-fabsf(d[3][1] + bs[col + 1]));
                    float e2 = __expf(-fabsf(d[3][2] + bs[col]));
                    float e3 = __expf(-fabsf(d[3][3] + bs[col + 1]));
                    *(float2*)&sf[orow * SFS + col]       = make_float2(e0, e1);
                    *(float2*)&sf[(orow + 8) * SFS + col] = make_float2(e2, e3);
                    *(uint2*)(g_aggT + (row0 + orow) * Aq + 2 * lq) =
                        make_uint2(f2tf32(e0), f2tf32(e1));
                    *(uint2*)(g_aggT + (row0 + orow + 8) * Aq + 2 * lq) =
                        make_uint2(f2tf32(e2), f2tf32(e3));
                }
            }
        }
        __syncthreads();

        // partial reduce: 4 subsets of 32 v; thread -> (a, f4 quad)
        {
            const int sub = tid / 144;
            const int t   = tid % 144;
            const int a8  = t & 7;
            const int f4  = t >> 3;
            const int vbase = sub * 32;

            float4 mx = make_float4(-INFINITY, -INFINITY, -INFINITY, -INFINITY);
            float4 sv = make_float4(0.f, 0.f, 0.f, 0.f);
#pragma unroll 8
            for (int i = 0; i < 32; i++) {
                const int v = vbase + i;
                float e = sf[v * SFS + 64 + a8];
                float4 x = *(float4*)&sf[v * SFS + f4 * 4];
                float p0 = e * x.x, p1 = e * x.y, p2 = e * x.z, p3 = e * x.w;
                mx.x = fmaxf(mx.x, p0); mx.y = fmaxf(mx.y, p1);
                mx.z = fmaxf(mx.z, p2); mx.w = fmaxf(mx.w, p3);
                sv.x += p0; sv.y += p1; sv.z += p2; sv.w += p3;
            }
            const int pc = chunk * 4 + sub;
            const long o = (((long)b * NPC + pc) * Aq + a8) * Fq + f4 * 4;
            *(float4*)(g_pmax + o) = mx;
            *(float4*)(g_psum + o) = sv;
        }
        __syncthreads();
    }
}

// ---------------------------------------------------------------------------
// kB2: combine partials -> collapsed[a,2F]; MT[b,n,a] tf32
// ---------------------------------------------------------------------------
__global__ void __launch_bounds__(576)
kB2(const float* __restrict__ Wout) {
    const int b = blockIdx.x;
    const int tid = threadIdx.x;
    const int a = tid % Aq;
    const int f = tid / Aq;

    __shared__ float scol[Aq][TWOF];

    {
        float vmax = -INFINITY, vsum = 0.f;
        const long base = ((long)b * NPC) * Aq * Fq + a * Fq + f;
#pragma unroll 8
        for (int pc = 0; pc < NPC; pc++) {
            vmax = fmaxf(vmax, g_pmax[base + (long)pc * Aq * Fq]);
            vsum += g_psum[base + (long)pc * Aq * Fq];
        }
        scol[a][f]      = vmax;
        scol[a][Fq + f] = vsum * (1.0f / (float)Vq);
    }
    __syncthreads();

    for (int idx = tid; idx < Aq * NFq; idx += 576) {
        int aa = idx / NFq, n = idx % NFq;
        float acc = Wout[(Pq + Aq * TWOF + aa) * NFq + n];
#pragma unroll 16
        for (int g = 0; g < TWOF; g++) {
            acc = fmaf(scol[aa][g], Wout[(Pq + aa * TWOF + g) * NFq + n], acc);
        }
        g_MT[((long)b * NFq + n) * Aq + aa] = f2tf32(acc);
    }
}

// ---------------------------------------------------------------------------
// k3: grid 256, 2 tiles (128 rows) per CTA, b constant per CTA -> Wt staged
// once. X raw via cp.async, A frags converted in registers after ldsm
// (agg cols already tf32: cvt idempotent). 512 threads = 16 warps (4m x 4n).
// ---------------------------------------------------------------------------
#define XS3 76
__global__ void __launch_bounds__(512)
k3(const float* __restrict__ X, const float* __restrict__ bout,
   float* __restrict__ out) {
    extern __shared__ uint32_t sm3[];
    uint32_t* Xs = sm3;                   // [128][76]: cols 0-63 X(raw), 64-71 agg(tf32)
    uint32_t* Wt = Xs + 128 * XS3;        // [128][76]
    float*    bC = (float*)(Wt + 128 * XS3);

    const int tid = threadIdx.x;
    const int bid = blockIdx.x;
    const int b   = bid >> 3;
    const int wid = tid >> 5, lane = tid & 31;
    const int wm = (wid >> 2) & 3, wn = wid & 3;
    const int lq = lane & 3, lg = lane >> 2;
    const int rA = lane & 15;
    const int cA = (lane & 16) >> 2;
    const int rB = (lane & 7) + ((lane & 16) >> 1);
    const int cB = (lane & 8) >> 1;

    // prologue: Wt (WoutT + MT) + tile-0 X/agg
    for (int i = tid; i < NFq * 16; i += 512) {
        int n = i >> 4, c = i & 15;
        cpasync16(s2u(Wt + n * XS3 + c * 4), g_WoutT + n * 64 + c * 4);
    }
    for (int i = tid; i < NFq * 2; i += 512) {
        int n = i >> 1, c = i & 1;
        cpasync16(s2u(Wt + n * XS3 + 64 + c * 4),
                  g_MT + ((long)b * NFq + n) * Aq + c * 4);
    }
    {
        const long row0 = (long)(bid * 2) * 128;
        for (int i = tid; i < 128 * 16; i += 512) {
            int r = i >> 4, c = i & 15;
            cpasync16(s2u(Xs + r * XS3 + c * 4), X + (row0 + r) * Pq + c * 4);
        }
        for (int i = tid; i < 128 * 2; i += 512) {
            int r = i >> 1, c = i & 1;
            cpasync16(s2u(Xs + r * XS3 + 64 + c * 4), g_aggT + (row0 + r) * Aq + c * 4);
        }
    }
    asm volatile("cp.async.commit_group;");
    if (tid < NFq) bC[tid] = bout[tid];

#pragma unroll
    for (int j = 0; j < 2; j++) {
        const int tile = bid * 2 + j;
        const long row0 = (long)tile * 128;

        asm volatile("cp.async.wait_group 0;");
        __syncthreads();

        uint32_t aAddr[2], bAddr[2];
#pragma unroll
        for (int mt = 0; mt < 2; mt++)
            aAddr[mt] = s2u(Xs + (wm * 32 + mt * 16 + rA) * XS3 + cA);
#pragma unroll
        for (int p = 0; p < 2; p++)
            bAddr[p] = s2u(Wt + (wn * 32 + p * 16 + rB) * XS3 + cB);

        float d[2][4][4];
#pragma unroll
        for (int mt = 0; mt < 2; mt++)
#pragma unroll
            for (int nt = 0; nt < 4; nt++)
#pragma unroll
                for (int r = 0; r < 4; r++) d[mt][nt][r] = 0.f;

#pragma unroll
        for (int ks = 0; ks < 9; ks++) {
            uint32_t a[2][4];
#pragma unroll
            for (int mt = 0; mt < 2; mt++) {
                ldsm4(a[mt], aAddr[mt]); aAddr[mt] += 32;
            }
#pragma unroll
            for (int mt = 0; mt < 2; mt++)
#pragma unroll
                for (int r = 0; r < 4; r++) a[mt][r] = cvt_reg(a[mt][r]);
            uint32_t bf[4][2];
#pragma unroll
            for (int p = 0; p < 2; p++) {
                ldsm4(&bf[2 * p][0], bAddr[p]); bAddr[p] += 32;
            }
#pragma unroll
            for (int mt = 0; mt < 2; mt++)
#pragma unroll
                for (int nt = 0; nt < 4; nt++)
                    mma_tf32(d[mt][nt], a[mt], bf[nt]);
        }
        __syncthreads();   // Xs reads done

        if (j == 0) {      // prefetch tile 1 X/agg; overlaps epilogue below
            const long nrow0 = (long)(tile + 1) * 128;
            for (int i = tid; i < 128 * 16; i += 512) {
                int r = i >> 4, c = i & 15;
                cpasync16(s2u(Xs + r * XS3 + c * 4), X + (nrow0 + r) * Pq + c * 4);
            }
            for (int i = tid; i < 128 * 2; i += 512) {
                int r = i >> 1, c = i & 1;
                cpasync16(s2u(Xs + r * XS3 + 64 + c * 4), g_aggT + (nrow0 + r) * Aq + c * 4);
            }
            asm volatile("cp.async.commit_group;");
        }

#pragma unroll
        for (int mt = 0; mt < 2; mt++) {
            const long r0 = row0 + wm * 32 + mt * 16 + lg;
#pragma unroll
            for (int nt = 0; nt < 4; nt++) {
                const int c0 = wn * 32 + nt * 8 + 2 * lq;
                float2 o0, o1;
                o0.x = ftanh(d[mt][nt][0] + bC[c0]);
                o0.y = ftanh(d[mt][nt][1] + bC[c0 + 1]);
                o1.x = ftanh(d[mt][nt][2] + bC[c0]);
                o1.y = ftanh(d[mt][nt][3] + bC[c0 + 1]);
                *(float2*)(out + (r0)     * NFq + c0) = o0;
                *(float2*)(out + (r0 + 8) * NFq + c0) = o1;
            }
        }
    }
}

// ---------------------------------------------------------------------------
extern "C" void kernel_launch(void* const* d_in, const int* in_sizes, int n_in,
                              void* d_out, int out_size) {
    const float* X    = (const float*)d_in[0];
    const float* W1   = (const float*)d_in[1];
    const float* b1   = (const float*)d_in[2];
    const float* W2   = (const float*)d_in[3];
    const float* b2   = (const float*)d_in[4];
    const float* Wout = (const float*)d_in[5];
    const float* bout = (const float*)d_in[6];
    float* out = (float*)d_out;

    const int smem1 = (2 * BUF1 + Fq * XS1 + 80) * 4;          // ~101.8 KB
    const int smem3 = (128 * XS3 * 2) * 4 + NFq * 4;           // ~78.3 KB
    cudaFuncSetAttribute(k1, cudaFuncAttributeMaxDynamicSharedMemorySize, smem1);
    cudaFuncSetAttribute(k3, cudaFuncAttributeMaxDynamicSharedMemorySize, smem3);

    kT<<<32, 256>>>(W1, W2, Wout);

    k1<<<(Bq * Vq) / 256, 576, smem1>>>(X, b1, b2);

    kB2<<<Bq, 576>>>(Wout);

    k3<<<(Bq * Vq) / 256, 512, smem3>>>(X, bout, out);
}

// round 15
// speedup vs baseline: 1.4545x; 1.0464x over previous
#include <cuda_runtime.h>
#include <math.h>
#include <stdint.h>

#define Bq 32
#define Vq 2048
#define Pq 64
#define Aq 8
#define Fq 72          // P + A
#define NFq 128
#define TWOF 144       // 2*F
#define NPC 64         // partial slots per batch (= 16 chunks * 4 subsets)

// Scratch (device globals; no allocation allowed)
__device__ uint32_t g_aggT [Bq * Vq * Aq];             // agg in tf32
__device__ uint32_t g_MT   [Bq * NFq * Aq];            // M transposed, tf32
__device__ uint32_t g_WoutT[NFq * 64];                 // [n][k] tf32 Wout_top^T
__device__ float    g_pmax [Bq * NPC * Aq * Fq];
__device__ float    g_psum [Bq * NPC * Aq * Fq];

__device__ __forceinline__ uint32_t f2tf32(float f) {
    uint32_t r; asm("cvt.rna.tf32.f32 %0, %1;" : "=r"(r) : "f"(f)); return r;
}
__device__ __forceinline__ void mma_tf32(float* d, const uint32_t* a, const uint32_t* b) {
    asm("mma.sync.aligned.m16n8k8.row.col.f32.tf32.tf32.f32 "
        "{%0,%1,%2,%3},{%4,%5,%6,%7},{%8,%9},{%0,%1,%2,%3};"
        : "+f"(d[0]), "+f"(d[1]), "+f"(d[2]), "+f"(d[3])
        : "r"(a[0]), "r"(a[1]), "r"(a[2]), "r"(a[3]), "r"(b[0]), "r"(b[1]));
}
__device__ __forceinline__ uint32_t s2u(const void* p) {
    return (uint32_t)__cvta_generic_to_shared(p);
}
__device__ __forceinline__ void ldsm4(uint32_t* r, uint32_t addr) {
    asm volatile("ldmatrix.sync.aligned.m8n8.x4.shared.b16 {%0,%1,%2,%3}, [%4];"
                 : "=r"(r[0]), "=r"(r[1]), "=r"(r[2]), "=r"(r[3]) : "r"(addr));
}
__device__ __forceinline__ void ldsm2(uint32_t* r, uint32_t addr) {
    asm volatile("ldmatrix.sync.aligned.m8n8.x2.shared.b16 {%0,%1}, [%2];"
                 : "=r"(r[0]), "=r"(r[1]) : "r"(addr));
}
__device__ __forceinline__ uint32_t cvt_reg(uint32_t raw) {
    return f2tf32(__uint_as_float(raw));
}
__device__ __forceinline__ float ftanh(float x) {
    float e = __expf(2.0f * x);
    return 1.0f - __fdividef(2.0f, e + 1.0f);
}
__device__ __forceinline__ void cpasync16(uint32_t dst, const void* src) {
    asm volatile("cp.async.cg.shared.global [%0], [%1], 16;" :: "r"(dst), "l"(src));
}

// ---------------------------------------------------------------------------
// k1: grid 256, 2 tiles (128 rows) per CTA, double-buffered raw-fp32 X via
// cp.async; A fragments converted to tf32 in registers after ldsm.
// Wt self-staged (coalesced LDG of W1/W2, transposed STS).
// Tail: CTAs 0-7 produce g_WoutT for k3. 576 threads = 18 warps.
// ---------------------------------------------------------------------------
#define XS1 68         // word stride of X rows
#define SFS 80         // float stride of feats tile
#define BUF1 10240     // words per X/sf buffer (128*80)
__global__ void __launch_bounds__(576)
k1(const float* __restrict__ X,
   const float* __restrict__ W1, const float* __restrict__ b1,
   const float* __restrict__ W2, const float* __restrict__ b2,
   const float* __restrict__ Wout) {
    extern __shared__ uint32_t smu[];
    uint32_t* Wt = smu + 2 * BUF1;            // [72][68]
    float*    bs = (float*)(Wt + Fq * XS1);   // [72]

    const int tid = threadIdx.x;
    const int bid = blockIdx.x;
    const int wid = tid >> 5, lane = tid & 31;
    const int lq = lane & 3, lg = lane >> 2;
    const int rA = lane & 15;
    const int cA = (lane & 16) >> 2;
    const int rB = (lane & 7) + ((lane & 16) >> 1);
    const int cB = (lane & 8) >> 1;

    // prologue: X copies first (fly during the W transpose below)
    {
        const float* src = X + (long)(bid * 2) * 128 * Pq;
        for (int i = tid; i < 128 * 16; i += 576) {
            int r = i >> 4, c = i & 15;
            cpasync16(s2u(smu + r * XS1 + c * 4), src + r * Pq + c * 4);
        }
    }
    asm volatile("cp.async.commit_group;");
    {
        const float* src = X + (long)(bid * 2 + 1) * 128 * Pq;
        for (int i = tid; i < 128 * 16; i += 576) {
            int r = i >> 4, c = i & 15;
            cpasync16(s2u(smu + BUF1 + r * XS1 + c * 4), src + r * Pq + c * 4);
        }
    }
    asm volatile("cp.async.commit_group;");

    // Wt self-stage: coalesced LDG, cvt, transposed STS
    {
        float v1[8];
#pragma unroll
        for (int t = 0; t < 8; t++) {
            int i = tid + t * 576;
            v1[t] = (i < 64 * 64) ? W1[i] : 0.f;
        }
        float v2 = (tid < 64 * Aq) ? W2[tid] : 0.f;
#pragma unroll
        for (int t = 0; t < 8; t++) {
            int i = tid + t * 576;
            if (i < 64 * 64) {
                int k = i >> 6, n = i & 63;
                Wt[n * XS1 + k] = f2tf32(v1[t]);
            }
        }
        if (tid < 64 * Aq) {
            int k = tid >> 3, n = tid & 7;
            Wt[(64 + n) * XS1 + k] = f2tf32(v2);
        }
    }
    if (tid < Fq) bs[tid] = (tid < Pq) ? b1[tid] : b2[tid - Pq];

#pragma unroll
    for (int j = 0; j < 2; j++) {
        const int tile = bid * 2 + j;
        const long row0 = (long)tile * 128;
        const int b = tile >> 4, chunk = tile & 15;
        uint32_t* xb = smu + j * BUF1;
        float*    sf = (float*)xb;

        if (j == 0) asm volatile("cp.async.wait_group 1;");
        else        asm volatile("cp.async.wait_group 0;");
        __syncthreads();

        float d[5][4];
        const int rg = wid & 7, wg = wid >> 3;
        if (wid < 16) {
            uint32_t aAddr = s2u(xb + (rg * 16 + rA) * XS1 + cA);
#pragma unroll
            for (int nt = 0; nt < 5; nt++)
#pragma unroll
                for (int r = 0; r < 4; r++) d[nt][r] = 0.f;

            if (wg == 0) {
                uint32_t b0  = s2u(Wt + (0  + rB) * XS1 + cB);
                uint32_t b1a = s2u(Wt + (16 + rB) * XS1 + cB);
                uint32_t b2a = s2u(Wt + (32 + (lane & 7)) * XS1 + cB);
#pragma unroll
                for (int ks = 0; ks < 8; ks++) {
                    uint32_t a[4];
                    ldsm4(a, aAddr); aAddr += 32;
#pragma unroll
                    for (int r = 0; r < 4; r++) a[r] = cvt_reg(a[r]);
                    uint32_t bf[5][2];
                    ldsm4(&bf[0][0], b0);  b0  += 32;
                    ldsm4(&bf[2][0], b1a); b1a += 32;
                    ldsm2(bf[4], b2a);     b2a += 32;
#pragma unroll
                    for (int nt = 0; nt < 5; nt++) mma_tf32(d[nt], a, bf[nt]);
                }
            } else {
                uint32_t b0  = s2u(Wt + (40 + rB) * XS1 + cB);
                uint32_t b1a = s2u(Wt + (56 + rB) * XS1 + cB);
#pragma unroll
                for (int ks = 0; ks < 8; ks++) {
                    uint32_t a[4];
                    ldsm4(a, aAddr); aAddr += 32;
#pragma unroll
                    for (int r = 0; r < 4; r++) a[r] = cvt_reg(a[r]);
                    uint32_t bf[4][2];
                    ldsm4(&bf[0][0], b0);  b0  += 32;
                    ldsm4(&bf[2][0], b1a); b1a += 32;
#pragma unroll
                    for (int nt = 0; nt < 4; nt++) mma_tf32(d[nt], a, bf[nt]);
                }
            }
        }
        __syncthreads();   // all X reads done; safe to overwrite with sf

        if (wid < 16) {
            const int orow = rg * 16 + lg;
            if (wg == 0) {
#pragma unroll
                for (int nt = 0; nt < 5; nt++) {
                    const int col = nt * 8 + 2 * lq;
                    *(float2*)&sf[orow * SFS + col] =
                        make_float2(d[nt][0] + bs[col], d[nt][1] + bs[col + 1]);
                    *(float2*)&sf[(orow + 8) * SFS + col] =
                        make_float2(d[nt][2] + bs[col], d[nt][3] + bs[col + 1]);
                }
            } else {
#pragma unroll
                for (int nt = 0; nt < 3; nt++) {
                    const int col = (nt + 5) * 8 + 2 * lq;
                    *(float2*)&sf[orow * SFS + col] =
                        make_float2(d[nt][0] + bs[col], d[nt][1] + bs[col + 1]);
                    *(float2*)&sf[(orow + 8) * SFS + col] =
                        make_float2(d[nt][2] + bs[col], d[nt][3] + bs[col + 1]);
                }
                {   // agg cols 64..71
                    const int col = 64 + 2 * lq;
                    float e0 = __expf(-fabsf(d[3][0] + bs[col]));
                    float e1 = __expf(-fabsf(d[3][1] + bs[col + 1]));
                    float e2 = __expf(-fabsf(d[3][2] + bs[col]));
                    float e3 = __expf(-fabsf(d[3][3] + bs[col + 1]));
                    *(float2*)&sf[orow * SFS + col]       = make_float2(e0, e1);
                    *(float2*)&sf[(orow + 8) * SFS + col] = make_float2(e2, e3);
                    *(uint2*)(g_aggT + (row0 + orow) * Aq + 2 * lq) =
                        make_uint2(f2tf32(e0), f2tf32(e1));
                    *(uint2*)(g_aggT + (row0 + orow + 8) * Aq + 2 * lq) =
                        make_uint2(f2tf32(e2), f2tf32(e3));
                }
            }
        }
        __syncthreads();

        // partial reduce: 4 subsets of 32 v; thread -> (a, f4 quad)
        {
            const int sub = tid / 144;
            const int t   = tid % 144;
            const int a8  = t & 7;
            const int f4  = t >> 3;
            const int vbase = sub * 32;

            float4 mx = make_float4(-INFINITY, -INFINITY, -INFINITY, -INFINITY);
            float4 sv = make_float4(0.f, 0.f, 0.f, 0.f);
#pragma unroll 8
            for (int i = 0; i < 32; i++) {
                const int v = vbase + i;
                float e = sf[v * SFS + 64 + a8];
                float4 x = *(float4*)&sf[v * SFS + f4 * 4];
                float p0 = e * x.x, p1 = e * x.y, p2 = e * x.z, p3 = e * x.w;
                mx.x = fmaxf(mx.x, p0); mx.y = fmaxf(mx.y, p1);
                mx.z = fmaxf(mx.z, p2); mx.w = fmaxf(mx.w, p3);
                sv.x += p0; sv.y += p1; sv.z += p2; sv.w += p3;
            }
            const int pc = chunk * 4 + sub;
            const long o = (((long)b * NPC + pc) * Aq + a8) * Fq + f4 * 4;
            *(float4*)(g_pmax + o) = mx;
            *(float4*)(g_psum + o) = sv;
        }
        __syncthreads();
    }

    // tail: CTAs 0-7 produce g_WoutT (n-major tf32 of Wout top 64 rows)
    if (bid < 8) {
        const int n0 = bid * 16;
        for (int i = tid; i < 64 * 16; i += 576) {
            int k = i >> 4, j = i & 15;        // coalesced 16-wide reads
            g_WoutT[(n0 + j) * 64 + k] = f2tf32(Wout[k * NFq + n0 + j]);
        }
    }
}

// ---------------------------------------------------------------------------
// kB2: combine partials -> collapsed[a,2F]; MT[b,n,a] tf32
// ---------------------------------------------------------------------------
__global__ void __launch_bounds__(576)
kB2(const float* __restrict__ Wout) {
    const int b = blockIdx.x;
    const int tid = threadIdx.x;
    const int a = tid % Aq;
    const int f = tid / Aq;

    __shared__ float scol[Aq][TWOF];

    {
        float vmax = -INFINITY, vsum = 0.f;
        const long base = ((long)b * NPC) * Aq * Fq + a * Fq + f;
#pragma unroll 8
        for (int pc = 0; pc < NPC; pc++) {
            vmax = fmaxf(vmax, g_pmax[base + (long)pc * Aq * Fq]);
            vsum += g_psum[base + (long)pc * Aq * Fq];
        }
        scol[a][f]      = vmax;
        scol[a][Fq + f] = vsum * (1.0f / (float)Vq);
    }
    __syncthreads();

    for (int idx = tid; idx < Aq * NFq; idx += 576) {
        int aa = idx / NFq, n = idx % NFq;
        float acc = Wout[(Pq + Aq * TWOF + aa) * NFq + n];
#pragma unroll 16
        for (int g = 0; g < TWOF; g++) {
            acc = fmaf(scol[aa][g], Wout[(Pq + aa * TWOF + g) * NFq + n], acc);
        }
        g_MT[((long)b * NFq + n) * Aq + aa] = f2tf32(acc);
    }
}

// ---------------------------------------------------------------------------
// k3: grid 256, 2 tiles (128 rows) per CTA, b constant per CTA -> Wt staged
// once. X raw via cp.async, A frags converted in registers after ldsm
// (agg cols already tf32: cvt idempotent). 512 threads = 16 warps (4m x 4n).
// ---------------------------------------------------------------------------
#define XS3 76
__global__ void __launch_bounds__(512)
k3(const float* __restrict__ X, const float* __restrict__ bout,
   float* __restrict__ out) {
    extern __shared__ uint32_t sm3[];
    uint32_t* Xs = sm3;                   // [128][76]: cols 0-63 X(raw), 64-71 agg(tf32)
    uint32_t* Wt = Xs + 128 * XS3;        // [128][76]
    float*    bC = (float*)(Wt + 128 * XS3);

    const int tid = threadIdx.x;
    const int bid = blockIdx.x;
    const int b   = bid >> 3;
    const int wid = tid >> 5, lane = tid & 31;
    const int wm = (wid >> 2) & 3, wn = wid & 3;
    const int lq = lane & 3, lg = lane >> 2;
    const int rA = lane & 15;
    const int cA = (lane & 16) >> 2;
    const int rB = (lane & 7) + ((lane & 16) >> 1);
    const int cB = (lane & 8) >> 1;

    // prologue: Wt (WoutT + MT) + tile-0 X/agg
    for (int i = tid; i < NFq * 16; i += 512) {
        int n = i >> 4, c = i & 15;
        cpasync16(s2u(Wt + n * XS3 + c * 4), g_WoutT + n * 64 + c * 4);
    }
    for (int i = tid; i < NFq * 2; i += 512) {
        int n = i >> 1, c = i & 1;
        cpasync16(s2u(Wt + n * XS3 + 64 + c * 4),
                  g_MT + ((long)b * NFq + n) * Aq + c * 4);
    }
    {
        const long row0 = (long)(bid * 2) * 128;
        for (int i = tid; i < 128 * 16; i += 512) {
            int r = i >> 4, c = i & 15;
            cpasync16(s2u(Xs + r * XS3 + c * 4), X + (row0 + r) * Pq + c * 4);
        }
        for (int i = tid; i < 128 * 2; i += 512) {
            int r = i >> 1, c = i & 1;
            cpasync16(s2u(Xs + r * XS3 + 64 + c * 4), g_aggT + (row0 + r) * Aq + c * 4);
        }
    }
    asm volatile("cp.async.commit_group;");
    if (tid < NFq) bC[tid] = bout[tid];

#pragma unroll
    for (int j = 0; j < 2; j++) {
        const int tile = bid * 2 + j;
        const long row0 = (long)tile * 128;

        asm volatile("cp.async.wait_group 0;");
        __syncthreads();

        uint32_t aAddr[2], bAddr[2];
#pragma unroll
        for (int mt = 0; mt < 2; mt++)
            aAddr[mt] = s2u(Xs + (wm * 32 + mt * 16 + rA) * XS3 + cA);
#pragma unroll
        for (int p = 0; p < 2; p++)
            bAddr[p] = s2u(Wt + (wn * 32 + p * 16 + rB) * XS3 + cB);

        float d[2][4][4];
#pragma unroll
        for (int mt = 0; mt < 2; mt++)
#pragma unroll
            for (int nt = 0; nt < 4; nt++)
#pragma unroll
                for (int r = 0; r < 4; r++) d[mt][nt][r] = 0.f;

#pragma unroll
        for (int ks = 0; ks < 9; ks++) {
            uint32_t a[2][4];
#pragma unroll
            for (int mt = 0; mt < 2; mt++) {
                ldsm4(a[mt], aAddr[mt]); aAddr[mt] += 32;
            }
#pragma unroll
            for (int mt = 0; mt < 2; mt++)
#pragma unroll
                for (int r = 0; r < 4; r++) a[mt][r] = cvt_reg(a[mt][r]);
            uint32_t bf[4][2];
#pragma unroll
            for (int p = 0; p < 2; p++) {
                ldsm4(&bf[2 * p][0], bAddr[p]); bAddr[p] += 32;
            }
#pragma unroll
            for (int mt = 0; mt < 2; mt++)
#pragma unroll
                for (int nt = 0; nt < 4; nt++)
                    mma_tf32(d[mt][nt], a[mt], bf[nt]);
        }
        __syncthreads();   // Xs reads done

        if (j == 0) {      // prefetch tile 1 X/agg; overlaps epilogue below
            const long nrow0 = (long)(tile + 1) * 128;
            for (int i = tid; i < 128 * 16; i += 512) {
                int r = i >> 4, c = i & 15;
                cpasync16(s2u(Xs + r * XS3 + c * 4), X + (nrow0 + r) * Pq + c * 4);
            }
            for (int i = tid; i < 128 * 2; i += 512) {
                int r = i >> 1, c = i & 1;
                cpasync16(s2u(Xs + r * XS3 + 64 + c * 4), g_aggT + (nrow0 + r) * Aq + c * 4);
            }
            asm volatile("cp.async.commit_group;");
        }

#pragma unroll
        for (int mt = 0; mt < 2; mt++) {
            const long r0 = row0 + wm * 32 + mt * 16 + lg;
#pragma unroll
            for (int nt = 0; nt < 4; nt++) {
                const int c0 = wn * 32 + nt * 8 + 2 * lq;
                float2 o0, o1;
                o0.x = ftanh(d[mt][nt][0] + bC[c0]);
                o0.y = ftanh(d[mt][nt][1] + bC[c0 + 1]);
                o1.x = ftanh(d[mt][nt][2] + bC[c0]);
                o1.y = ftanh(d[mt][nt][3] + bC[c0 + 1]);
                *(float2*)(out + (r0)     * NFq + c0) = o0;
                *(float2*)(out + (r0 + 8) * NFq + c0) = o1;
            }
        }
    }
}

// ---------------------------------------------------------------------------
extern "C" void kernel_launch(void* const* d_in, const int* in_sizes, int n_in,
                              void* d_out, int out_size) {
    const float* X    = (const float*)d_in[0];
    const float* W1   = (const float*)d_in[1];
    const float* b1   = (const float*)d_in[2];
    const float* W2   = (const float*)d_in[3];
    const float* b2   = (const float*)d_in[4];
    const float* Wout = (const float*)d_in[5];
    const float* bout = (const float*)d_in[6];
    float* out = (float*)d_out;

    const int smem1 = (2 * BUF1 + Fq * XS1 + 80) * 4;          // ~101.8 KB
    const int smem3 = (128 * XS3 * 2) * 4 + NFq * 4;           // ~78.3 KB
    cudaFuncSetAttribute(k1, cudaFuncAttributeMaxDynamicSharedMemorySize, smem1);
    cudaFuncSetAttribute(k3, cudaFuncAttributeMaxDynamicSharedMemorySize, smem3);

    k1<<<(Bq * Vq) / 256, 576, smem1>>>(X, W1, b1, W2, b2, Wout);

    kB2<<<Bq, 576>>>(Wout);

    k3<<<(Bq * Vq) / 256, 512, smem3>>>(X, bout, out);
}

// round 16
// speedup vs baseline: 1.5854x; 1.0900x over previous
#include <cuda_runtime.h>
#include <cuda_fp16.h>
#include <math.h>
#include <stdint.h>

#define Bq 32
#define Vq 2048
#define Pq 64
#define Aq 8
#define Fq 72          // P + A
#define NFq 128
#define TWOF 144       // 2*F
#define NPC 64         // partial slots per batch (= 16 chunks * 4 subsets)

// Scratch (device globals; no allocation allowed)
__device__ __half g_aggH [Bq * Vq * Aq];               // agg fp16
__device__ __half g_MTh  [Bq * NFq * Aq];              // M transposed fp16
__device__ __half g_WoutH[NFq * 64];                   // [n][k] fp16 Wout_top^T
__device__ float  g_pmax [Bq * NPC * Aq * Fq];
__device__ float  g_psum [Bq * NPC * Aq * Fq];

__device__ __forceinline__ void mma_f16(float* d, const uint32_t* a, const uint32_t* b) {
    asm("mma.sync.aligned.m16n8k16.row.col.f32.f16.f16.f32 "
        "{%0,%1,%2,%3},{%4,%5,%6,%7},{%8,%9},{%0,%1,%2,%3};"
        : "+f"(d[0]), "+f"(d[1]), "+f"(d[2]), "+f"(d[3])
        : "r"(a[0]), "r"(a[1]), "r"(a[2]), "r"(a[3]), "r"(b[0]), "r"(b[1]));
}
__device__ __forceinline__ uint32_t s2u(const void* p) {
    return (uint32_t)__cvta_generic_to_shared(p);
}
__device__ __forceinline__ void ldsm4(uint32_t* r, uint32_t addr) {
    asm volatile("ldmatrix.sync.aligned.m8n8.x4.shared.b16 {%0,%1,%2,%3}, [%4];"
                 : "=r"(r[0]), "=r"(r[1]), "=r"(r[2]), "=r"(r[3]) : "r"(addr));
}
__device__ __forceinline__ void ldsm2(uint32_t* r, uint32_t addr) {
    asm volatile("ldmatrix.sync.aligned.m8n8.x2.shared.b16 {%0,%1}, [%2];"
                 : "=r"(r[0]), "=r"(r[1]) : "r"(addr));
}
__device__ __forceinline__ uint32_t pack_h2(float a, float b) {
    __half2 h = __floats2half2_rn(a, b);
    return *(uint32_t*)&h;
}
__device__ __forceinline__ float ftanh(float x) {
    float e = __expf(2.0f * x);
    return 1.0f - __fdividef(2.0f, e + 1.0f);
}
__device__ __forceinline__ void cpasync16(uint32_t dst, const void* src) {
    asm volatile("cp.async.cg.shared.global [%0], [%1], 16;" :: "r"(dst), "l"(src));
}

// ---------------------------------------------------------------------------
// k1: grid 256, 2 tiles (128 rows) per CTA. Raw fp32 X double-buffered via
// cp.async; per-tile convert pass -> fp16 A tile; fp16 m16n8k16 MMA (4 ksteps).
// Wt (fp16, n-major) self-staged from W1/W2. Tail: CTAs 0-7 emit g_WoutH.
// 576 threads = 18 warps. MMA: warps 0-15 (8 rg x 2 ng). Reduce: 4 subsets.
// ---------------------------------------------------------------------------
#define XS1 68         // raw X float stride
#define SFS 80         // float stride of feats tile
#define BUF1 10240     // words per raw/sf buffer (128*80)
#define XH1 72         // fp16 A tile half-stride (144 B)
#define WS1 72         // fp16 Wt half-stride (144 B)
__global__ void __launch_bounds__(576, 2)
k1(const float* __restrict__ X,
   const float* __restrict__ W1, const float* __restrict__ b1,
   const float* __restrict__ W2, const float* __restrict__ b2,
   const float* __restrict__ Wout) {
    extern __shared__ uint32_t smu[];
    __half* Xh  = (__half*)(smu + 2 * BUF1);          // [128][72] halves
    __half* Wt1 = Xh + 128 * XH1;                     // [72][72] halves
    float*  bs  = (float*)(Wt1 + Fq * WS1);           // [72]

    const int tid = threadIdx.x;
    const int bid = blockIdx.x;
    const int wid = tid >> 5, lane = tid & 31;
    const int lq = lane & 3, lg = lane >> 2;
    const int rA = lane & 15;
    const int cA = (lane & 16) >> 1;                  // halves
    const int rB = (lane & 7) + ((lane & 16) >> 1);
    const int cB = (lane & 8);                        // halves

    // prologue: X raw copies first (fly during the W staging below)
    {
        const float* src = X + (long)(bid * 2) * 128 * Pq;
        for (int i = tid; i < 128 * 16; i += 576) {
            int r = i >> 4, c = i & 15;
            cpasync16(s2u(smu + r * XS1 + c * 4), src + r * Pq + c * 4);
        }
    }
    asm volatile("cp.async.commit_group;");
    {
        const float* src = X + (long)(bid * 2 + 1) * 128 * Pq;
        for (int i = tid; i < 128 * 16; i += 576) {
            int r = i >> 4, c = i & 15;
            cpasync16(s2u(smu + BUF1 + r * XS1 + c * 4), src + r * Pq + c * 4);
        }
    }
    asm volatile("cp.async.commit_group;");

    // Wt self-stage: coalesced LDG, cvt fp16, transposed STS
    {
        float v1[8];
#pragma unroll
        for (int t = 0; t < 8; t++) {
            int i = tid + t * 576;
            v1[t] = (i < 64 * 64) ? W1[i] : 0.f;
        }
        float v2 = (tid < 64 * Aq) ? W2[tid] : 0.f;
#pragma unroll
        for (int t = 0; t < 8; t++) {
            int i = tid + t * 576;
            if (i < 64 * 64) {
                int k = i >> 6, n = i & 63;
                Wt1[n * WS1 + k] = __float2half_rn(v1[t]);
            }
        }
        if (tid < 64 * Aq) {
            int k = tid >> 3, n = tid & 7;
            Wt1[(64 + n) * WS1 + k] = __float2half_rn(v2);
        }
    }
    if (tid < Fq) bs[tid] = (tid < Pq) ? b1[tid] : b2[tid - Pq];

#pragma unroll
    for (int j = 0; j < 2; j++) {
        const int tile = bid * 2 + j;
        const long row0 = (long)tile * 128;
        const int b = tile >> 4, chunk = tile & 15;
        uint32_t* xb = smu + j * BUF1;
        float*    sf = (float*)xb;

        if (j == 0) asm volatile("cp.async.wait_group 1;");
        else        asm volatile("cp.async.wait_group 0;");
        __syncthreads();

        // convert raw fp32 -> fp16 A tile
        for (int i = tid; i < 128 * 16; i += 576) {
            int r = i >> 4, c = i & 15;
            float4 v = *(const float4*)((const float*)xb + r * XS1 + c * 4);
            *(uint2*)(Xh + r * XH1 + c * 4) =
                make_uint2(pack_h2(v.x, v.y), pack_h2(v.z, v.w));
        }
        __syncthreads();

        float d[5][4];
        const int rg = wid & 7, wg = wid >> 3;
        if (wid < 16) {
            uint32_t aAddr = s2u(Xh + (rg * 16 + rA) * XH1 + cA);
#pragma unroll
            for (int nt = 0; nt < 5; nt++)
#pragma unroll
                for (int r = 0; r < 4; r++) d[nt][r] = 0.f;

            if (wg == 0) {
                uint32_t b0  = s2u(Wt1 + (0  + rB) * WS1 + cB);
                uint32_t b1a = s2u(Wt1 + (16 + rB) * WS1 + cB);
                uint32_t b2a = s2u(Wt1 + (32 + (lane & 7)) * WS1 + cB);
#pragma unroll
                for (int ks = 0; ks < 4; ks++) {
                    uint32_t a[4];
                    ldsm4(a, aAddr); aAddr += 32;
                    uint32_t bf[5][2];
                    ldsm4(&bf[0][0], b0);  b0  += 32;
                    ldsm4(&bf[2][0], b1a); b1a += 32;
                    ldsm2(bf[4], b2a);     b2a += 32;
#pragma unroll
                    for (int nt = 0; nt < 5; nt++) mma_f16(d[nt], a, bf[nt]);
                }
            } else {
                uint32_t b0  = s2u(Wt1 + (40 + rB) * WS1 + cB);
                uint32_t b1a = s2u(Wt1 + (56 + rB) * WS1 + cB);
#pragma unroll
                for (int ks = 0; ks < 4; ks++) {
                    uint32_t a[4];
                    ldsm4(a, aAddr); aAddr += 32;
                    uint32_t bf[4][2];
                    ldsm4(&bf[0][0], b0);  b0  += 32;
                    ldsm4(&bf[2][0], b1a); b1a += 32;
#pragma unroll
                    for (int nt = 0; nt < 4; nt++) mma_f16(d[nt], a, bf[nt]);
                }
            }
        }
        __syncthreads();   // raw X + Xh reads done; safe to overwrite xb with sf

        if (wid < 16) {
            const int orow = rg * 16 + lg;
            if (wg == 0) {
#pragma unroll
                for (int nt = 0; nt < 5; nt++) {
                    const int col = nt * 8 + 2 * lq;
                    *(float2*)&sf[orow * SFS + col] =
                        make_float2(d[nt][0] + bs[col], d[nt][1] + bs[col + 1]);
                    *(float2*)&sf[(orow + 8) * SFS + col] =
                        make_float2(d[nt][2] + bs[col], d[nt][3] + bs[col + 1]);
                }
            } else {
#pragma unroll
                for (int nt = 0; nt < 3; nt++) {
                    const int col = (nt + 5) * 8 + 2 * lq;
                    *(float2*)&sf[orow * SFS + col] =
                        make_float2(d[nt][0] + bs[col], d[nt][1] + bs[col + 1]);
                    *(float2*)&sf[(orow + 8) * SFS + col] =
                        make_float2(d[nt][2] + bs[col], d[nt][3] + bs[col + 1]);
                }
                {   // agg cols 64..71
                    const int col = 64 + 2 * lq;
                    float e0 = __expf(-fabsf(d[3][0] + bs[col]));
                    float e1 = __expf(-fabsf(d[3][1] + bs[col + 1]));
                    float e2 = __expf(-fabsf(d[3][2] + bs[col]));
                    float e3 = __expf(-fabsf(d[3][3] + bs[col + 1]));
                    *(float2*)&sf[orow * SFS + col]       = make_float2(e0, e1);
                    *(float2*)&sf[(orow + 8) * SFS + col] = make_float2(e2, e3);
                    *(uint32_t*)(g_aggH + (row0 + orow) * Aq + 2 * lq)     = pack_h2(e0, e1);
                    *(uint32_t*)(g_aggH + (row0 + orow + 8) * Aq + 2 * lq) = pack_h2(e2, e3);
                }
            }
        }
        __syncthreads();

        // partial reduce: 4 subsets of 32 v; thread -> (a, f4 quad)
        {
            const int sub = tid / 144;
            const int t   = tid % 144;
            const int a8  = t & 7;
            const int f4  = t >> 3;
            const int vbase = sub * 32;

            float4 mx = make_float4(-INFINITY, -INFINITY, -INFINITY, -INFINITY);
            float4 sv = make_float4(0.f, 0.f, 0.f, 0.f);
#pragma unroll 8
            for (int i = 0; i < 32; i++) {
                const int v = vbase + i;
                float e = sf[v * SFS + 64 + a8];
                float4 x = *(float4*)&sf[v * SFS + f4 * 4];
                float p0 = e * x.x, p1 = e * x.y, p2 = e * x.z, p3 = e * x.w;
                mx.x = fmaxf(mx.x, p0); mx.y = fmaxf(mx.y, p1);
                mx.z = fmaxf(mx.z, p2); mx.w = fmaxf(mx.w, p3);
                sv.x += p0; sv.y += p1; sv.z += p2; sv.w += p3;
            }
            const int pc = chunk * 4 + sub;
            const long o = (((long)b * NPC + pc) * Aq + a8) * Fq + f4 * 4;
            *(float4*)(g_pmax + o) = mx;
            *(float4*)(g_psum + o) = sv;
        }
        __syncthreads();
    }

    // tail: CTAs 0-7 produce g_WoutH (n-major fp16 of Wout top 64 rows)
    if (bid < 8) {
        const int n0 = bid * 16;
        for (int i = tid; i < 64 * 16; i += 576) {
            int k = i >> 4, j = i & 15;
            g_WoutH[(n0 + j) * 64 + k] = __float2half_rn(Wout[k * NFq + n0 + j]);
        }
    }
}

// ---------------------------------------------------------------------------
// kB2: combine partials -> collapsed[a,2F]; MTh[b,n,a] fp16
// ---------------------------------------------------------------------------
__global__ void __launch_bounds__(576)
kB2(const float* __restrict__ Wout) {
    const int b = blockIdx.x;
    const int tid = threadIdx.x;
    const int a = tid % Aq;
    const int f = tid / Aq;

    __shared__ float scol[Aq][TWOF];

    {
        float vmax = -INFINITY, vsum = 0.f;
        const long base = ((long)b * NPC) * Aq * Fq + a * Fq + f;
#pragma unroll 8
        for (int pc = 0; pc < NPC; pc++) {
            vmax = fmaxf(vmax, g_pmax[base + (long)pc * Aq * Fq]);
            vsum += g_psum[base + (long)pc * Aq * Fq];
        }
        scol[a][f]      = vmax;
        scol[a][Fq + f] = vsum * (1.0f / (float)Vq);
    }
    __syncthreads();

    for (int idx = tid; idx < Aq * NFq; idx += 576) {
        int aa = idx / NFq, n = idx % NFq;
        float acc = Wout[(Pq + Aq * TWOF + aa) * NFq + n];
#pragma unroll 16
        for (int g = 0; g < TWOF; g++) {
            acc = fmaf(scol[aa][g], Wout[(Pq + aa * TWOF + g) * NFq + n], acc);
        }
        g_MTh[((long)b * NFq + n) * Aq + aa] = __float2half_rn(acc);
    }
}

// ---------------------------------------------------------------------------
// k3: grid 256, 2 tiles (128 rows) per CTA, b constant per CTA. fp16
// m16n8k16 MMA, K padded 72->80 (5 ksteps). Raw X via cp.async + convert
// pass; agg/Wt fp16 via cp.async. 512 threads = 16 warps (4m x 4n).
// ---------------------------------------------------------------------------
#define XR3 68         // raw X float stride
#define XM3 88         // fp16 A tile half-stride (176 B)
#define WS3 88         // fp16 Wt half-stride (176 B)
__global__ void __launch_bounds__(512, 2)
k3(const float* __restrict__ X, const float* __restrict__ bout,
   float* __restrict__ out) {
    extern __shared__ uint32_t sm3[];
    float*  raw = (float*)sm3;                        // [128][68] fp32
    __half* Xm0 = (__half*)(raw + 128 * XR3);         // [128][88] halves
    __half* Xm1 = Xm0 + 128 * XM3;
    __half* WtH = Xm1 + 128 * XM3;                    // [128][88] halves
    float*  bC  = (float*)(WtH + 128 * WS3);          // [128]

    const int tid = threadIdx.x;
    const int bid = blockIdx.x;
    const int b   = bid >> 3;
    const int wid = tid >> 5, lane = tid & 31;
    const int wm = (wid >> 2) & 3, wn = wid & 3;
    const int lq = lane & 3, lg = lane >> 2;
    const int rA = lane & 15;
    const int cA = (lane & 16) >> 1;                  // halves
    const int rB = (lane & 7) + ((lane & 16) >> 1);
    const int cB = (lane & 8);                        // halves

    // prologue group 0: Wt (WoutH + MTh), agg for both tiles, raw X tile 0
    for (int i = tid; i < NFq * 8; i += 512) {
        int n = i >> 3, c = i & 7;
        cpasync16(s2u(WtH + n * WS3 + c * 8), g_WoutH + n * 64 + c * 8);
    }
    for (int i = tid; i < NFq; i += 512) {
        cpasync16(s2u(WtH + i * WS3 + 64), g_MTh + ((long)b * NFq + i) * Aq);
    }
    {
        const long row0 = (long)(bid * 2) * 128;
        for (int r = tid; r < 128; r += 512) {
            cpasync16(s2u(Xm0 + r * XM3 + 64), g_aggH + (row0 + r) * Aq);
            cpasync16(s2u(Xm1 + r * XM3 + 64), g_aggH + (row0 + 128 + r) * Aq);
        }
        for (int i = tid; i < 128 * 16; i += 512) {
            int r = i >> 4, c = i & 15;
            cpasync16(s2u(raw + r * XR3 + c * 4), X + (row0 + r) * Pq + c * 4);
        }
    }
    asm volatile("cp.async.commit_group;");
    // zero pads (k 72..79) for both A tiles and Wt
    {
        uint4 z = make_uint4(0, 0, 0, 0);
        for (int r = tid; r < 128; r += 512) {
            *(uint4*)(Xm0 + r * XM3 + 72) = z;
            *(uint4*)(Xm1 + r * XM3 + 72) = z;
            *(uint4*)(WtH + r * WS3 + 72) = z;
        }
    }
    if (tid < NFq) bC[tid] = bout[tid];

#pragma unroll
    for (int j = 0; j < 2; j++) {
        const int tile = bid * 2 + j;
        const long row0 = (long)tile * 128;
        __half* Xm = (j == 0) ? Xm0 : Xm1;

        asm volatile("cp.async.wait_group 0;");
        __syncthreads();

        // convert raw fp32 -> fp16 (cols 0..63)
        for (int i = tid; i < 128 * 16; i += 512) {
            int r = i >> 4, c = i & 15;
            float4 v = *(const float4*)(raw + r * XR3 + c * 4);
            *(uint2*)(Xm + r * XM3 + c * 4) =
                make_uint2(pack_h2(v.x, v.y), pack_h2(v.z, v.w));
        }
        __syncthreads();

        if (j == 0) {   // prefetch raw X of tile 1 (overlaps MMA + epilogue)
            const long nrow0 = (long)(tile + 1) * 128;
            for (int i = tid; i < 128 * 16; i += 512) {
                int r = i >> 4, c = i & 15;
                cpasync16(s2u(raw + r * XR3 + c * 4), X + (nrow0 + r) * Pq + c * 4);
            }
            asm volatile("cp.async.commit_group;");
        }

        uint32_t aAddr[2], bAddr[2];
#pragma unroll
        for (int mt = 0; mt < 2; mt++)
            aAddr[mt] = s2u(Xm + (wm * 32 + mt * 16 + rA) * XM3 + cA);
#pragma unroll
        for (int p = 0; p < 2; p++)
            bAddr[p] = s2u(WtH + (wn * 32 + p * 16 + rB) * WS3 + cB);

        float d[2][4][4];
#pragma unroll
        for (int mt = 0; mt < 2; mt++)
#pragma unroll
            for (int nt = 0; nt < 4; nt++)
#pragma unroll
                for (int r = 0; r < 4; r++) d[mt][nt][r] = 0.f;

#pragma unroll
        for (int ks = 0; ks < 5; ks++) {
            uint32_t a[2][4];
#pragma unroll
            for (int mt = 0; mt < 2; mt++) {
                ldsm4(a[mt], aAddr[mt]); aAddr[mt] += 32;
            }
            uint32_t bf[4][2];
#pragma unroll
            for (int p = 0; p < 2; p++) {
                ldsm4(&bf[2 * p][0], bAddr[p]); bAddr[p] += 32;
            }
#pragma unroll
            for (int mt = 0; mt < 2; mt++)
#pragma unroll
                for (int nt = 0; nt < 4; nt++)
                    mma_f16(d[mt][nt], a[mt], bf[nt]);
        }

#pragma unroll
        for (int mt = 0; mt < 2; mt++) {
            const long r0 = row0 + wm * 32 + mt * 16 + lg;
#pragma unroll
            for (int nt = 0; nt < 4; nt++) {
                const int c0 = wn * 32 + nt * 8 + 2 * lq;
                float2 o0, o1;
                o0.x = ftanh(d[mt][nt][0] + bC[c0]);
                o0.y = ftanh(d[mt][nt][1] + bC[c0 + 1]);
                o1.x = ftanh(d[mt][nt][2] + bC[c0]);
                o1.y = ftanh(d[mt][nt][3] + bC[c0 + 1]);
                *(float2*)(out + (r0)     * NFq + c0) = o0;
                *(float2*)(out + (r0 + 8) * NFq + c0) = o1;
            }
        }
        __syncthreads();   // Xm/raw reuse safety before next tile
    }
}

// ---------------------------------------------------------------------------
extern "C" void kernel_launch(void* const* d_in, const int* in_sizes, int n_in,
                              void* d_out, int out_size) {
    const float* X    = (const float*)d_in[0];
    const float* W1   = (const float*)d_in[1];
    const float* b1   = (const float*)d_in[2];
    const float* W2   = (const float*)d_in[3];
    const float* b2   = (const float*)d_in[4];
    const float* Wout = (const float*)d_in[5];
    const float* bout = (const float*)d_in[6];
    float* out = (float*)d_out;

    const int smem1 = 2 * BUF1 * 4 + 128 * XH1 * 2 + Fq * WS1 * 2 + Fq * 4;  // ~108.4 KB
    const int smem3 = 128 * XR3 * 4 + 2 * 128 * XM3 * 2 + 128 * WS3 * 2 + NFq * 4;  // ~100.5 KB
    cudaFuncSetAttribute(k1, cudaFuncAttributeMaxDynamicSharedMemorySize, smem1);
    cudaFuncSetAttribute(k3, cudaFuncAttributeMaxDynamicSharedMemorySize, smem3);

    k1<<<(Bq * Vq) / 256, 576, smem1>>>(X, W1, b1, W2, b2, Wout);

    kB2<<<Bq, 576>>>(Wout);

    k3<<<(Bq * Vq) / 256, 512, smem3>>>(X, bout, out);
}